// round 1
// baseline (speedup 1.0000x reference)
#include <cuda_runtime.h>

// Problem constants
#define BB 512
#define TT 365
#define CC 10
#define PP 64
#define KK (TT * CC)      // 3650
#define KSPLIT 15
#define KCHUNK 256        // 15*256 = 3840 >= 3650

// Scratch (allocation-free: __device__ globals)
__device__ float g_mx[BB * KK];            // masked input, 7.5 MB
__device__ float g_x2[BB];                 // sum mask*x^2 per b
__device__ float g_psqT[TT * PP];          // [t][p] sum_c proto^2
__device__ float g_part[KSPLIT * BB * PP]; // split-K partials of xp
__device__ int   g_idx[BB];                // argmin indices

// ---------------------------------------------------------------------------
// prep1: per-b — build mx = x*mask, reduce x2, and fuse input/mask passthrough
// ---------------------------------------------------------------------------
__global__ __launch_bounds__(256) void prep1_kernel(
    const float* __restrict__ x, const float* __restrict__ mask,
    float* __restrict__ out_in, float* __restrict__ out_mask)
{
    int b = blockIdx.x;
    int tid = threadIdx.x;
    __shared__ float smask[TT];
    for (int t = tid; t < TT; t += 256) {
        float m = mask[b * TT + t];
        smask[t] = m;
        out_mask[b * TT + t] = m;
    }
    __syncthreads();

    float acc = 0.0f;
    const float* xb = x + (size_t)b * KK;
    float* mxb = g_mx + (size_t)b * KK;
    float* oib = out_in + (size_t)b * KK;
    for (int i = tid; i < KK; i += 256) {
        float xv = xb[i];
        float mv = smask[i / CC];
        float mx = xv * mv;
        mxb[i] = mx;
        oib[i] = xv;
        acc = fmaf(mx, xv, acc);   // mask * x^2
    }
    // block reduce
    #pragma unroll
    for (int off = 16; off > 0; off >>= 1)
        acc += __shfl_down_sync(0xffffffffu, acc, off);
    __shared__ float red[8];
    if ((tid & 31) == 0) red[tid >> 5] = acc;
    __syncthreads();
    if (tid < 8) {
        float v = red[tid];
        #pragma unroll
        for (int off = 4; off > 0; off >>= 1)
            v += __shfl_down_sync(0xffu, v, off);
        if (tid == 0) g_x2[b] = v;
    }
}

// ---------------------------------------------------------------------------
// prep2: psqT[t][p] = sum_c proto[p][t][c]^2
// ---------------------------------------------------------------------------
__global__ __launch_bounds__(256) void prep2_kernel(const float* __restrict__ proto)
{
    int lin = blockIdx.x * 256 + threadIdx.x;
    if (lin >= TT * PP) return;
    int p = lin & (PP - 1);
    int t = lin >> 6;   // PP == 64
    const float* pr = proto + (size_t)p * KK + t * CC;
    float s = 0.0f;
    #pragma unroll
    for (int c = 0; c < CC; c++) s = fmaf(pr[c], pr[c], s);
    g_psqT[t * PP + p] = s;
}

// ---------------------------------------------------------------------------
// gemm: split-K tiled  xp_part[ks][b][p] = sum_{k in chunk} mx[b][k]*proto[p][k]
// 64x64 tile, 256 threads, 4x4 micro-tile, 32-deep smem stages
// ---------------------------------------------------------------------------
__global__ __launch_bounds__(256) void gemm_kernel(const float* __restrict__ proto)
{
    const int mb = blockIdx.x * 64;   // batch tile base
    const int ks = blockIdx.y;        // k-split index
    const int tid = threadIdx.x;
    const int m0 = (tid >> 4) * 4;    // 0..60
    const int p0 = (tid & 15) * 4;    // 0..60

    __shared__ float As[32][68];      // pad 68 to limit store conflicts
    __shared__ float Bs[32][68];

    float acc[4][4];
    #pragma unroll
    for (int i = 0; i < 4; i++)
        #pragma unroll
        for (int j = 0; j < 4; j++) acc[i][j] = 0.0f;

    const int kbeg = ks * KCHUNK;
    const int kend = (kbeg + KCHUNK < KK) ? (kbeg + KCHUNK) : KK;

    for (int k0 = kbeg; k0 < kend; k0 += 32) {
        // stage 32x64 of each operand; 8 elems/thread, 128B-coalesced gmem
        #pragma unroll
        for (int j = 0; j < 8; j++) {
            int l = tid + j * 256;       // 0..2047
            int kk = l & 31;
            int mm = l >> 5;             // 0..63
            int k = k0 + kk;
            float av = 0.0f, bv = 0.0f;
            if (k < KK) {
                av = g_mx[(size_t)(mb + mm) * KK + k];
                bv = proto[(size_t)mm * KK + k];
            }
            As[kk][mm] = av;
            Bs[kk][mm] = bv;
        }
        __syncthreads();
        #pragma unroll
        for (int kk = 0; kk < 32; kk++) {
            float4 a4 = *reinterpret_cast<const float4*>(&As[kk][m0]);
            float4 b4 = *reinterpret_cast<const float4*>(&Bs[kk][p0]);
            float av[4] = {a4.x, a4.y, a4.z, a4.w};
            float bv[4] = {b4.x, b4.y, b4.z, b4.w};
            #pragma unroll
            for (int i = 0; i < 4; i++)
                #pragma unroll
                for (int j = 0; j < 4; j++)
                    acc[i][j] = fmaf(av[i], bv[j], acc[i][j]);
        }
        __syncthreads();
    }

    float* dst = g_part + (size_t)ks * BB * PP;
    #pragma unroll
    for (int i = 0; i < 4; i++) {
        float4 v = make_float4(acc[i][0], acc[i][1], acc[i][2], acc[i][3]);
        *reinterpret_cast<float4*>(&dst[(size_t)(mb + m0 + i) * PP + p0]) = v;
    }
}

// ---------------------------------------------------------------------------
// finalize: distances, argmin (first-min tie-break), indices/label outputs
// ---------------------------------------------------------------------------
__global__ __launch_bounds__(64) void finalize_kernel(
    const float* __restrict__ mask, const int* __restrict__ label,
    float* __restrict__ out_dist, float* __restrict__ out_idx,
    float* __restrict__ out_lab)
{
    int b = blockIdx.x;
    int p = threadIdx.x;   // 0..63

    __shared__ float smask[TT];
    for (int t = p; t < TT; t += 64) smask[t] = mask[b * TT + t];
    __syncthreads();

    float xp = 0.0f;
    #pragma unroll
    for (int ks = 0; ks < KSPLIT; ks++)
        xp += g_part[((size_t)ks * BB + b) * PP + p];

    float p2 = 0.0f;
    for (int t = 0; t < TT; t++)
        p2 = fmaf(smask[t], g_psqT[t * PP + p], p2);

    float d = g_x2[b] - 2.0f * xp + p2;
    out_dist[b * PP + p] = d;

    // argmin over 64 with first-index tie-break
    float dv = d;
    unsigned iv = (unsigned)p;
    #pragma unroll
    for (int off = 16; off > 0; off >>= 1) {
        float od = __shfl_down_sync(0xffffffffu, dv, off);
        unsigned oi = __shfl_down_sync(0xffffffffu, iv, off);
        if (od < dv || (od == dv && oi < iv)) { dv = od; iv = oi; }
    }
    __shared__ float rd[2];
    __shared__ unsigned ri[2];
    if ((p & 31) == 0) { rd[p >> 5] = dv; ri[p >> 5] = iv; }
    __syncthreads();
    if (p == 0) {
        float d0 = rd[0]; unsigned i0 = ri[0];
        if (rd[1] < d0 || (rd[1] == d0 && ri[1] < i0)) { d0 = rd[1]; i0 = ri[1]; }
        g_idx[b] = (int)i0;
        out_idx[b] = (float)i0;
        out_lab[b] = (float)label[b];
    }
}

// ---------------------------------------------------------------------------
// gather: output_seq[b] = proto[idx[b]]
// ---------------------------------------------------------------------------
__global__ __launch_bounds__(256) void gather_kernel(
    const float* __restrict__ proto, float* __restrict__ out_seq)
{
    int b = blockIdx.x;
    int idx = g_idx[b];
    const float* src = proto + (size_t)idx * KK;
    float* dst = out_seq + (size_t)b * KK;
    for (int i = threadIdx.x; i < KK; i += 256) dst[i] = src[i];
}

// ---------------------------------------------------------------------------
extern "C" void kernel_launch(void* const* d_in, const int* in_sizes, int n_in,
                              void* d_out, int out_size)
{
    const float* x     = (const float*)d_in[0];  // [512,365,10]
    const float* mask  = (const float*)d_in[1];  // [512,365]
    const int*   label = (const int*)  d_in[2];  // [512]
    const float* proto = (const float*)d_in[3];  // [64,365,10]

    float* out = (float*)d_out;
    float* out_seq  = out;                          // [512,365,10]
    float* out_in   = out_seq  + (size_t)BB * KK;   // [512,365,10]
    float* out_dist = out_in   + (size_t)BB * KK;   // [512,64]
    float* out_idx  = out_dist + (size_t)BB * PP;   // [512]
    float* out_lab  = out_idx  + BB;                // [512]
    float* out_mask = out_lab  + BB;                // [512,365]

    prep1_kernel<<<BB, 256>>>(x, mask, out_in, out_mask);
    prep2_kernel<<<(TT * PP + 255) / 256, 256>>>(proto);
    gemm_kernel<<<dim3(BB / 64, KSPLIT), 256>>>(proto);
    finalize_kernel<<<BB, 64>>>(mask, label, out_dist, out_idx, out_lab);
    gather_kernel<<<BB, 256>>>(proto, out_seq);
}